// round 11
// baseline (speedup 1.0000x reference)
#include <cuda_runtime.h>
#include <cuda_fp16.h>
#include <math.h>

#define NN 50000
#define EE 1600000
#define ET (EE + NN)
#define GG 100
#define IN_CH 16
#define H1 4
#define C1 32
#define D1 (H1*C1)
#define C2 32
#define NEG 0.2f

#define DEG_BLOCKS ((EE + 255) / 256)
#define SCAT_BLOCKS ((ET + 255) / 256)
#define GEMM1_BLOCKS ((NN + 63) / 64)

// ---------------- scratch ----------------
__device__ __align__(16) int g_deg[NN + 4];
__device__ __align__(16) int g_rowptr[NN + 4];
__device__ __align__(16) int g_cursor[NN + 4];
__device__ __align__(16) int g_csrsrc[ET];
__device__ __align__(16) __half g_h1h[NN * D1];
__device__ __align__(16) float  g_as1[NN * H1];
__device__ __align__(16) float  g_ad1[NN * H1];
__device__ __align__(16) __half g_out1h[NN * D1];
__device__ __align__(16) __half g_h2h[NN * C2];
__device__ float g_as2[NN];
__device__ float g_ad2[NN];
__device__ float g_pool[GG * C2];
__device__ float g_cnt[GG];

// ---------------- degree + pool init ----------------
__global__ void k_degree(const int* __restrict__ ei) {
    int b = blockIdx.x;
    if (b < DEG_BLOCKS) {
        int e = b * 256 + threadIdx.x;
        if (e < EE) atomicAdd(&g_deg[ei[EE + e]], 1);
    } else {
        int i = threadIdx.x;
        for (; i < GG * C2; i += 256) g_pool[i] = 0.f;
        int j = threadIdx.x;
        if (j < GG) g_cnt[j] = 0.f;
    }
}

// ---------------- single-block exclusive scan, 4 elems/thread ----------------
__global__ void k_scan() {
    __shared__ int warp_sums[32];
    __shared__ int carry_s;
    int t = threadIdx.x;
    int lane = t & 31, warp = t >> 5;
    if (t == 0) carry_s = 0;
    __syncthreads();
    const int CHUNK = 4096;
    for (int base = 0; base < NN; base += CHUNK) {
        int idx = base + t * 4;
        int4 v4 = make_int4(0, 0, 0, 0);
        if (idx < NN) {
            v4 = *(const int4*)(g_deg + idx);
            *(int4*)(g_deg + idx) = make_int4(0, 0, 0, 0);
            v4.x += 1; v4.y += 1; v4.z += 1; v4.w += 1;   // self loops
        }
        int v = v4.x + v4.y + v4.z + v4.w;
        int incl = v;
        #pragma unroll
        for (int off = 1; off < 32; off <<= 1) {
            int nb = __shfl_up_sync(0xffffffffu, incl, off);
            if (lane >= off) incl += nb;
        }
        if (lane == 31) warp_sums[warp] = incl;
        __syncthreads();
        if (warp == 0) {
            int ws = warp_sums[lane];
            int wincl = ws;
            #pragma unroll
            for (int off = 1; off < 32; off <<= 1) {
                int nb = __shfl_up_sync(0xffffffffu, wincl, off);
                if (lane >= off) wincl += nb;
            }
            warp_sums[lane] = wincl - ws;
        }
        __syncthreads();
        int carry = carry_s;
        int excl = carry + warp_sums[warp] + incl - v;
        if (idx < NN) {
            int4 r;
            r.x = excl;
            r.y = r.x + v4.x;
            r.z = r.y + v4.y;
            r.w = r.z + v4.z;
            *(int4*)(g_rowptr + idx) = r;
            *(int4*)(g_cursor + idx) = r;
        }
        __syncthreads();
        if (t == 1023) carry_s = carry + warp_sums[31] + incl;
        __syncthreads();
    }
    if (t == 0) g_rowptr[NN] = carry_s;
}

// ---------------- GEMM1 body ----------------
__device__ __forceinline__ void gemm1_body(int blk,
                        const float* __restrict__ x,
                        const float* __restrict__ W1,
                        const float* __restrict__ as_w,
                        const float* __restrict__ ad_w,
                        float* sW, float* sAs, float* sAd) {
    int t = threadIdx.x;
    for (int i = t; i < IN_CH * D1; i += 256) sW[i] = W1[i];
    if (t < H1 * C1) { sAs[t] = as_w[t]; sAd[t] = ad_w[t]; }
    __syncthreads();

    int warp = t >> 5, lane = t & 31;
    int h = warp & 3;
    int n = blk * 64 + (warp >> 2) * 32 + lane;
    if (n >= NN) return;

    float xv[16];
    const float4* xp = (const float4*)(x + (size_t)n * IN_CH);
    #pragma unroll
    for (int i = 0; i < 4; i++) {
        float4 r = xp[i];
        xv[4*i]=r.x; xv[4*i+1]=r.y; xv[4*i+2]=r.z; xv[4*i+3]=r.w;
    }
    float acc[C1];
    #pragma unroll
    for (int c = 0; c < C1; c++) acc[c] = 0.f;
    #pragma unroll
    for (int k = 0; k < IN_CH; k++) {
        float xk = xv[k];
        const float* wrow = sW + k * D1 + h * C1;
        #pragma unroll
        for (int c = 0; c < C1; c++) acc[c] += xk * wrow[c];
    }
    float asum = 0.f, dsum = 0.f;
    #pragma unroll
    for (int c = 0; c < C1; c++) { asum += acc[c] * sAs[h*C1+c]; dsum += acc[c] * sAd[h*C1+c]; }
    g_as1[n * H1 + h] = asum;
    g_ad1[n * H1 + h] = dsum;
    uint4 pk[4];
    unsigned* pu = (unsigned*)pk;
    #pragma unroll
    for (int i = 0; i < 16; i++) {
        __half2 hh = __floats2half2_rn(acc[2*i], acc[2*i+1]);
        pu[i] = *(unsigned*)&hh;
    }
    uint4* hp = (uint4*)(g_h1h + (size_t)n * D1 + h * C1);
    #pragma unroll
    for (int i = 0; i < 4; i++) hp[i] = pk[i];
}

// ---------------- scatter + gemm1 fat kernel ----------------
__global__ void __launch_bounds__(256) k_scatter_gemm1(
        const int* __restrict__ ei,
        const float* __restrict__ x,
        const float* __restrict__ W1,
        const float* __restrict__ as_w,
        const float* __restrict__ ad_w) {
    __shared__ float sW[IN_CH * D1 + 2 * H1 * C1];
    int b = blockIdx.x;
    if (b < SCAT_BLOCKS) {
        int idx = b * 256 + threadIdx.x;
        if (idx >= ET) return;
        int src, dst;
        if (idx < EE) { src = ei[idx]; dst = ei[EE + idx]; }
        else          { src = idx - EE; dst = src; }
        int slot = atomicAdd(&g_cursor[dst], 1);
        g_csrsrc[slot] = src;
    } else {
        gemm1_body(b - SCAT_BLOCKS, x, W1, as_w, ad_w,
                   sW, sW + IN_CH * D1, sW + IN_CH * D1 + H1 * C1);
    }
}

__device__ __forceinline__ float lrelu(float e) { return e > 0.f ? e : NEG * e; }
__device__ __forceinline__ float elu(float v)   { return v > 0.f ? v : (__expf(v) - 1.f); }

__device__ __forceinline__ float sel4(float4 a, int q) {
    float w = a.x;
    w = (q == 1) ? a.y : w;
    w = (q == 2) ? a.z : w;
    w = (q == 3) ? a.w : w;
    return w;
}

__device__ __forceinline__ int h2bits(float v) {
    __half2 h = __float2half2_rn(v);
    return *(int*)&h;
}

// ---------------- GAT layer 1: HFMA2 phase B, byte offsets, block=128 ----------------
__global__ void __launch_bounds__(128) k_edge1(const float* __restrict__ b1) {
    __shared__ int2 s_pk[4][32][4];   // [warp][edge][head] = (row byte offset, alpha half2)
    int w = threadIdx.x >> 5;
    int lane = threadIdx.x & 31;
    int n = blockIdx.x * 4 + w;
    if (n >= NN) return;
    int beg = g_rowptr[n], end = g_rowptr[n + 1];
    float4 ad = *(const float4*)(g_ad1 + n * 4);
    const char* hbase = (const char*)g_h1h;

    int grp = lane >> 4;
    int sub = lane & 15;
    int q2  = sub >> 2;
    int choff2 = sub * 16;          // byte offset within row (8 halves)

    float s0 = 0.f, s1 = 0.f, s2 = 0.f, s3 = 0.f;
    float a[8];
    #pragma unroll
    for (int k = 0; k < 8; k++) a[k] = 0.f;

    for (int base = beg; base < end; base += 32) {
        int i = base + lane;
        int cnt = min(32, end - base);
        // Phase A: lane-parallel exp, pack (byteoff, half2 alpha)
        if (i < end) {
            int s = g_csrsrc[i];
            float4 as = *(const float4*)(g_as1 + s * 4);
            float e0 = __expf(lrelu(as.x + ad.x));
            float e1 = __expf(lrelu(as.y + ad.y));
            float e2 = __expf(lrelu(as.z + ad.z));
            float e3 = __expf(lrelu(as.w + ad.w));
            s0 += e0; s1 += e1; s2 += e2; s3 += e3;
            int boff = s * (D1 * 2);
            s_pk[w][lane][0] = make_int2(boff, h2bits(e0));
            s_pk[w][lane][1] = make_int2(boff, h2bits(e1));
            s_pk[w][lane][2] = make_int2(boff, h2bits(e2));
            s_pk[w][lane][3] = make_int2(boff, h2bits(e3));
        }
        __syncwarp();
        // Phase B: HFMA2 accumulation into tile-local half2 regs
        __half2 h0 = __float2half2_rn(0.f), h1v = h0, h2v = h0, h3v = h0;
        int j = 0;
        for (; j + 4 <= cnt; j += 4) {
            int2 pkA = s_pk[w][j + grp][q2];
            int2 pkB = s_pk[w][j + 2 + grp][q2];
            uint4 pA = *(const uint4*)(hbase + pkA.x + choff2);
            uint4 pB = *(const uint4*)(hbase + pkB.x + choff2);
            __half2 wA = *(__half2*)&pkA.y;
            __half2 wB = *(__half2*)&pkB.y;
            h0 = __hfma2(wA, *(__half2*)&pA.x, h0);
            h1v = __hfma2(wA, *(__half2*)&pA.y, h1v);
            h2v = __hfma2(wA, *(__half2*)&pA.z, h2v);
            h3v = __hfma2(wA, *(__half2*)&pA.w, h3v);
            h0 = __hfma2(wB, *(__half2*)&pB.x, h0);
            h1v = __hfma2(wB, *(__half2*)&pB.y, h1v);
            h2v = __hfma2(wB, *(__half2*)&pB.z, h2v);
            h3v = __hfma2(wB, *(__half2*)&pB.w, h3v);
        }
        for (; j + 2 <= cnt; j += 2) {
            int2 pk = s_pk[w][j + grp][q2];
            uint4 p = *(const uint4*)(hbase + pk.x + choff2);
            __half2 wj = *(__half2*)&pk.y;
            h0 = __hfma2(wj, *(__half2*)&p.x, h0);
            h1v = __hfma2(wj, *(__half2*)&p.y, h1v);
            h2v = __hfma2(wj, *(__half2*)&p.z, h2v);
            h3v = __hfma2(wj, *(__half2*)&p.w, h3v);
        }
        if (j < cnt && grp == 0) {
            int2 pk = s_pk[w][j][q2];
            uint4 p = *(const uint4*)(hbase + pk.x + choff2);
            __half2 wj = *(__half2*)&pk.y;
            h0 = __hfma2(wj, *(__half2*)&p.x, h0);
            h1v = __hfma2(wj, *(__half2*)&p.y, h1v);
            h2v = __hfma2(wj, *(__half2*)&p.z, h2v);
            h3v = __hfma2(wj, *(__half2*)&p.w, h3v);
        }
        // flush tile-local fp16 accumulators to fp32
        float2 f;
        f = __half22float2(h0);  a[0] += f.x; a[1] += f.y;
        f = __half22float2(h1v); a[2] += f.x; a[3] += f.y;
        f = __half22float2(h2v); a[4] += f.x; a[5] += f.y;
        f = __half22float2(h3v); a[6] += f.x; a[7] += f.y;
        __syncwarp();
    }
    #pragma unroll
    for (int k = 0; k < 8; k++) a[k] += __shfl_xor_sync(0xffffffffu, a[k], 16);
    #pragma unroll
    for (int off = 16; off; off >>= 1) {
        s0 += __shfl_xor_sync(0xffffffffu, s0, off);
        s1 += __shfl_xor_sync(0xffffffffu, s1, off);
        s2 += __shfl_xor_sync(0xffffffffu, s2, off);
        s3 += __shfl_xor_sync(0xffffffffu, s3, off);
    }
    if (grp == 0) {
        float inv = sel4(make_float4(1.f/(s0+1e-16f), 1.f/(s1+1e-16f),
                                     1.f/(s2+1e-16f), 1.f/(s3+1e-16f)), q2);
        const float* bp = b1 + sub * 8;
        uint4 pko;
        unsigned* pu = (unsigned*)&pko;
        #pragma unroll
        for (int k = 0; k < 4; k++) {
            float v0 = elu(a[2*k]   * inv + bp[2*k]);
            float v1 = elu(a[2*k+1] * inv + bp[2*k+1]);
            __half2 hh = __floats2half2_rn(v0, v1);
            pu[k] = *(unsigned*)&hh;
        }
        *(uint4*)(g_out1h + (size_t)n * D1 + sub * 8) = pko;
    }
}

// ---------------- GEMM2 + attention logits (fp16 in, fp16 out) ----------------
__global__ void k_gemm2(const float* __restrict__ W2,
                        const float* __restrict__ as_w,
                        const float* __restrict__ ad_w) {
    __shared__ float sW[D1 * C2];
    __shared__ float sAs[C2], sAd[C2];
    int t = threadIdx.x;
    for (int i = t; i < D1 * C2; i += 256) sW[i] = W2[i];
    if (t < C2) { sAs[t] = as_w[t]; sAd[t] = ad_w[t]; }
    __syncthreads();
    int n = blockIdx.x * blockDim.x + t;
    if (n >= NN) return;

    float acc[C2];
    #pragma unroll
    for (int c = 0; c < C2; c++) acc[c] = 0.f;
    const uint4* xp = (const uint4*)(g_out1h + (size_t)n * D1);
    #pragma unroll 2
    for (int k8 = 0; k8 < 16; k8++) {
        uint4 u = xp[k8];
        float2 f0 = __half22float2(*(__half2*)&u.x);
        float2 f1 = __half22float2(*(__half2*)&u.y);
        float2 f2 = __half22float2(*(__half2*)&u.z);
        float2 f3 = __half22float2(*(__half2*)&u.w);
        const float* w0 = sW + (k8 * 8) * C2;
        #pragma unroll
        for (int c = 0; c < C2; c++) {
            acc[c] += f0.x * w0[c]        + f0.y * w0[C2 + c]
                    + f1.x * w0[2*C2 + c] + f1.y * w0[3*C2 + c]
                    + f2.x * w0[4*C2 + c] + f2.y * w0[5*C2 + c]
                    + f3.x * w0[6*C2 + c] + f3.y * w0[7*C2 + c];
        }
    }
    float asum = 0.f, dsum = 0.f;
    #pragma unroll
    for (int c = 0; c < C2; c++) { asum += acc[c] * sAs[c]; dsum += acc[c] * sAd[c]; }
    g_as2[n] = asum;
    g_ad2[n] = dsum;
    uint4 pk[2];
    unsigned* pu = (unsigned*)pk;
    #pragma unroll
    for (int i = 0; i < 8; i++) {
        __half2 hh = __floats2half2_rn(acc[2*i], acc[2*i+1]);
        pu[i] = *(unsigned*)&hh;
    }
    uint4* hp = (uint4*)(g_h2h + (size_t)n * C2);
    hp[0] = pk[0]; hp[1] = pk[1];
    uint4 pk2[2];
    unsigned* pu2 = (unsigned*)pk2;
    #pragma unroll
    for (int i = 0; i < 8; i++) {
        __half2 hh = __floats2half2_rn(acc[16 + 2*i], acc[16 + 2*i + 1]);
        pu2[i] = *(unsigned*)&hh;
    }
    hp[2] = pk2[0]; hp[3] = pk2[1];
}

// ---------------- GAT layer 2 + pooling: HFMA2, 2 edges/warp-iter ----------------
__global__ void __launch_bounds__(128) k_edge2(const float* __restrict__ b2,
                        const int* __restrict__ batch) {
    __shared__ int2 s_pk[4][32];    // (row byte offset, alpha half2)
    int w = threadIdx.x >> 5;
    int lane = threadIdx.x & 31;
    int n = blockIdx.x * 4 + w;
    if (n >= NN) return;
    int beg = g_rowptr[n], end = g_rowptr[n + 1];
    float ad = g_ad2[n];
    const char* hbase = (const char*)g_h2h;

    int grp = lane >> 4;
    int sub = lane & 15;
    int choff2 = sub * 4;           // byte offset (2 halves)

    float ssum = 0.f;
    float a0 = 0.f, a1 = 0.f;
    for (int base = beg; base < end; base += 32) {
        int i = base + lane;
        int cnt = min(32, end - base);
        if (i < end) {
            int s = g_csrsrc[i];
            float e = __expf(lrelu(g_as2[s] + ad));
            ssum += e;
            s_pk[w][lane] = make_int2(s * (C2 * 2), h2bits(e));
        }
        __syncwarp();
        __half2 hacc = __float2half2_rn(0.f);
        int j = 0;
        for (; j + 4 <= cnt; j += 4) {
            int2 pkA = s_pk[w][j + grp];
            int2 pkB = s_pk[w][j + 2 + grp];
            unsigned uA = *(const unsigned*)(hbase + pkA.x + choff2);
            unsigned uB = *(const unsigned*)(hbase + pkB.x + choff2);
            hacc = __hfma2(*(__half2*)&pkA.y, *(__half2*)&uA, hacc);
            hacc = __hfma2(*(__half2*)&pkB.y, *(__half2*)&uB, hacc);
        }
        for (; j + 2 <= cnt; j += 2) {
            int2 pk = s_pk[w][j + grp];
            unsigned u = *(const unsigned*)(hbase + pk.x + choff2);
            hacc = __hfma2(*(__half2*)&pk.y, *(__half2*)&u, hacc);
        }
        if (j < cnt && grp == 0) {
            int2 pk = s_pk[w][j];
            unsigned u = *(const unsigned*)(hbase + pk.x + choff2);
            hacc = __hfma2(*(__half2*)&pk.y, *(__half2*)&u, hacc);
        }
        float2 f = __half22float2(hacc);
        a0 += f.x; a1 += f.y;
        __syncwarp();
    }
    a0 += __shfl_xor_sync(0xffffffffu, a0, 16);
    a1 += __shfl_xor_sync(0xffffffffu, a1, 16);
    #pragma unroll
    for (int off = 16; off; off >>= 1) ssum += __shfl_xor_sync(0xffffffffu, ssum, off);
    float inv = 1.f / (ssum + 1e-16f);
    int gid = batch[n];
    if (grp == 0) {
        float v0 = elu(a0 * inv + b2[sub * 2]);
        float v1 = elu(a1 * inv + b2[sub * 2 + 1]);
        float* pp = g_pool + gid * C2 + sub * 2;
        atomicAdd(pp,     v0);
        atomicAdd(pp + 1, v1);
        if (sub == 0) atomicAdd(&g_cnt[gid], 1.0f);
    }
}

// ---------------- MLP head ----------------
__global__ void k_head(const float* __restrict__ Wh1, const float* __restrict__ bh1,
                       const float* __restrict__ Wh2, const float* __restrict__ bh2,
                       float* __restrict__ out) {
    int g = blockIdx.x * blockDim.x + threadIdx.x;
    if (g >= GG) return;
    float cnt = fmaxf(g_cnt[g], 1.0f);
    float invc = 1.f / cnt;
    float p[C2];
    #pragma unroll
    for (int c = 0; c < C2; c++) p[c] = g_pool[g * C2 + c] * invc;
    float o = bh2[0];
    for (int j = 0; j < 64; j++) {
        float a = bh1[j];
        #pragma unroll
        for (int c = 0; c < C2; c++) a += p[c] * Wh1[c * 64 + j];
        a = fmaxf(a, 0.f);
        o += a * Wh2[j];
    }
    out[g] = o;
}

// ---------------- launch ----------------
extern "C" void kernel_launch(void* const* d_in, const int* in_sizes, int n_in,
                              void* d_out, int out_size) {
    const float* x     = (const float*)d_in[0];
    const int*   ei    = (const int*)d_in[1];
    const int*   batch = (const int*)d_in[2];
    const float* W1   = (const float*)d_in[3];
    const float* as1  = (const float*)d_in[4];
    const float* ad1  = (const float*)d_in[5];
    const float* b1   = (const float*)d_in[6];
    const float* W2   = (const float*)d_in[7];
    const float* as2  = (const float*)d_in[8];
    const float* ad2  = (const float*)d_in[9];
    const float* b2   = (const float*)d_in[10];
    const float* Wh1  = (const float*)d_in[11];
    const float* bh1  = (const float*)d_in[12];
    const float* Wh2  = (const float*)d_in[13];
    const float* bh2  = (const float*)d_in[14];
    float* out = (float*)d_out;

    k_degree<<<DEG_BLOCKS + 1, 256>>>(ei);
    k_scan<<<1, 1024>>>();
    k_scatter_gemm1<<<SCAT_BLOCKS + GEMM1_BLOCKS, 256>>>(ei, x, W1, as1, ad1);
    k_edge1<<<(NN + 3) / 4, 128>>>(b1);
    k_gemm2<<<(NN + 255) / 256, 256>>>(W2, as2, ad2);
    k_edge2<<<(NN + 3) / 4, 128>>>(b2, batch);
    k_head<<<1, 128>>>(Wh1, bh1, Wh2, bh2, out);
}